// round 1
// baseline (speedup 1.0000x reference)
#include <cuda_runtime.h>
#include <math.h>
#include <stdint.h>

// ---------------------------------------------------------------------------
// NetGIN: 5-layer GIN (eps=0) + per-graph mean readout, fully fused.
//
// Algebra: (x + agg)@W1 + b1 = z + segment_sum(z[src]) + b1,  z = x@W1.
// => ALL edge aggregation happens in dim-10 projected space (even layer 1,
//    whose raw input is dim-64).
//
// Buffers: z ping-pong + agg, stride 12 floats (48B, 16B-aligned rows).
// Scatter uses red.global.add.{v4,v2}.f32 (no return, L2-side reduction).
// Readout: per-node scalar r = x_l . l_l accumulated atomically per graph.
// ---------------------------------------------------------------------------

#define NMAX   500000
#define STRIDE 12
#define DIM    10
#define GMAX   8192

__device__ __align__(16) float g_zA[NMAX * STRIDE];
__device__ __align__(16) float g_zB[NMAX * STRIDE];
__device__ __align__(16) float g_agg[NMAX * STRIDE];
__device__ float g_s[GMAX];
__device__ float g_cnt[GMAX];

// ---------------- init / readout helpers ----------------

__global__ void zero_graph_kernel(float* s, float* cnt, int G) {
    int i = blockIdx.x * blockDim.x + threadIdx.x;
    if (i < G) { s[i] = 0.0f; cnt[i] = 0.0f; }
}

__global__ void count_kernel(const int* __restrict__ ng, float* cnt, int n) {
    int i = blockIdx.x * blockDim.x + threadIdx.x;
    if (i < n) atomicAdd(&cnt[ng[i]], 1.0f);
}

__global__ void final_kernel(const float* __restrict__ s,
                             const float* __restrict__ cnt,
                             float* __restrict__ out, int G) {
    int i = blockIdx.x * blockDim.x + threadIdx.x;
    if (i < G) {
        float v = s[i] / fmaxf(cnt[i], 1.0f);
        out[i] = 1.0f / (1.0f + expf(-v));
    }
}

// ---------------- layer-1 projection: z = h @ W1 (64 -> 10) ----------------

__global__ void proj1_kernel(const float* __restrict__ h,
                             const float* __restrict__ W1,
                             float* __restrict__ z, int n) {
    int i = blockIdx.x * blockDim.x + threadIdx.x;
    if (i >= n) return;
    float acc[DIM];
#pragma unroll
    for (int d = 0; d < DIM; d++) acc[d] = 0.0f;

    const float4* hp = reinterpret_cast<const float4*>(h + (size_t)i * 64);
#pragma unroll
    for (int k4 = 0; k4 < 16; k4++) {
        float4 hv = __ldg(&hp[k4]);
        int k = k4 * 4;
#pragma unroll
        for (int d = 0; d < DIM; d++) {
            acc[d] += hv.x * W1[(k + 0) * DIM + d];
            acc[d] += hv.y * W1[(k + 1) * DIM + d];
            acc[d] += hv.z * W1[(k + 2) * DIM + d];
            acc[d] += hv.w * W1[(k + 3) * DIM + d];
        }
    }
    float* zp = z + (size_t)i * STRIDE;
#pragma unroll
    for (int d = 0; d < DIM; d++) zp[d] = acc[d];
}

// ---------------- edge aggregation: agg[dst] += z[src] (dim 10) -------------

__global__ void edge_kernel(const float* __restrict__ z,
                            float* __restrict__ agg,
                            const int* __restrict__ src,
                            const int* __restrict__ dst, int E_) {
    int e = blockIdx.x * blockDim.x + threadIdx.x;
    if (e >= E_) return;
    int s = __ldg(&src[e]);
    int d = __ldg(&dst[e]);
    const float* zs = z + (size_t)s * STRIDE;
    float4 a = *reinterpret_cast<const float4*>(zs);
    float4 b = *reinterpret_cast<const float4*>(zs + 4);
    float2 c = *reinterpret_cast<const float2*>(zs + 8);
    float* ad = agg + (size_t)d * STRIDE;
    asm volatile("red.global.add.v4.f32 [%0], {%1,%2,%3,%4};"
                 :: "l"(ad), "f"(a.x), "f"(a.y), "f"(a.z), "f"(a.w) : "memory");
    asm volatile("red.global.add.v4.f32 [%0], {%1,%2,%3,%4};"
                 :: "l"(ad + 4), "f"(b.x), "f"(b.y), "f"(b.z), "f"(b.w) : "memory");
    asm volatile("red.global.add.v2.f32 [%0], {%1,%2};"
                 :: "l"(ad + 8), "f"(c.x), "f"(c.y) : "memory");
}

// ---------------- fused node MLP + readout + next-layer projection ----------
// u = relu(z + agg + b1); o = relu(u @ W2 + b2);
// s[graph] += o . lvec; z_next = o @ W1_next (if any).

__global__ void node_kernel(const float* __restrict__ z,
                            const float* __restrict__ agg,
                            const float* __restrict__ b1,
                            const float* __restrict__ W2,
                            const float* __restrict__ b2,
                            const float* __restrict__ lvec,
                            const float* __restrict__ W1n,  // null on last layer
                            float* __restrict__ znext,
                            const int* __restrict__ ng,
                            float* __restrict__ sAcc, int n) {
    int i = blockIdx.x * blockDim.x + threadIdx.x;
    if (i >= n) return;

    const float* zp = z + (size_t)i * STRIDE;
    const float* ap = agg + (size_t)i * STRIDE;

    float u[DIM];
    {
        float4 z0 = *reinterpret_cast<const float4*>(zp);
        float4 z1 = *reinterpret_cast<const float4*>(zp + 4);
        float2 z2 = *reinterpret_cast<const float2*>(zp + 8);
        float4 a0 = *reinterpret_cast<const float4*>(ap);
        float4 a1 = *reinterpret_cast<const float4*>(ap + 4);
        float2 a2 = *reinterpret_cast<const float2*>(ap + 8);
        u[0] = fmaxf(z0.x + a0.x + b1[0], 0.0f);
        u[1] = fmaxf(z0.y + a0.y + b1[1], 0.0f);
        u[2] = fmaxf(z0.z + a0.z + b1[2], 0.0f);
        u[3] = fmaxf(z0.w + a0.w + b1[3], 0.0f);
        u[4] = fmaxf(z1.x + a1.x + b1[4], 0.0f);
        u[5] = fmaxf(z1.y + a1.y + b1[5], 0.0f);
        u[6] = fmaxf(z1.z + a1.z + b1[6], 0.0f);
        u[7] = fmaxf(z1.w + a1.w + b1[7], 0.0f);
        u[8] = fmaxf(z2.x + a2.x + b1[8], 0.0f);
        u[9] = fmaxf(z2.y + a2.y + b1[9], 0.0f);
    }

    float o[DIM];
#pragma unroll
    for (int d = 0; d < DIM; d++) {
        float acc = b2[d];
#pragma unroll
        for (int k = 0; k < DIM; k++) acc += u[k] * W2[k * DIM + d];
        o[d] = fmaxf(acc, 0.0f);
    }

    float r = 0.0f;
#pragma unroll
    for (int d = 0; d < DIM; d++) r += o[d] * lvec[d];
    atomicAdd(&sAcc[ng[i]], r);

    if (W1n != nullptr) {
        float* zn = znext + (size_t)i * STRIDE;
#pragma unroll
        for (int d = 0; d < DIM; d++) {
            float acc = 0.0f;
#pragma unroll
            for (int k = 0; k < DIM; k++) acc += o[k] * W1n[k * DIM + d];
            zn[d] = acc;
        }
    }
}

// ---------------------------------------------------------------------------

extern "C" void kernel_launch(void* const* d_in, const int* in_sizes, int n_in,
                              void* d_out, int out_size) {
    const float* h   = (const float*)d_in[0];
    const int*   src = (const int*)d_in[1];
    const int*   dst = (const int*)d_in[2];
    const int*   ng  = (const int*)d_in[3];

    const float *W1[5], *b1[5], *W2[5], *b2[5], *lv[5];
    for (int i = 0; i < 5; i++) {
        W1[i] = (const float*)d_in[4 + 5 * i + 0];
        b1[i] = (const float*)d_in[4 + 5 * i + 1];
        W2[i] = (const float*)d_in[4 + 5 * i + 2];
        b2[i] = (const float*)d_in[4 + 5 * i + 3];
        lv[i] = (const float*)d_in[4 + 5 * i + 4];
    }

    int N = in_sizes[3];   // node_graph has N elements
    int E = in_sizes[1];   // src has E elements
    int G = out_size;      // one sigmoid per graph
    float* out = (float*)d_out;

    float *zA, *zB, *agg, *sAcc, *cnt;
    cudaGetSymbolAddress((void**)&zA,   g_zA);
    cudaGetSymbolAddress((void**)&zB,   g_zB);
    cudaGetSymbolAddress((void**)&agg,  g_agg);
    cudaGetSymbolAddress((void**)&sAcc, g_s);
    cudaGetSymbolAddress((void**)&cnt,  g_cnt);

    const int BT = 256;

    zero_graph_kernel<<<(G + BT - 1) / BT, BT>>>(sAcc, cnt, G);
    count_kernel<<<(N + BT - 1) / BT, BT>>>(ng, cnt, N);
    proj1_kernel<<<(N + 127) / 128, 128>>>(h, W1[0], zA, N);

    float* zin = zA;
    float* zout = zB;
    for (int l = 0; l < 5; l++) {
        cudaMemsetAsync(agg, 0, (size_t)N * STRIDE * sizeof(float), 0);
        edge_kernel<<<(E + BT - 1) / BT, BT>>>(zin, agg, src, dst, E);
        node_kernel<<<(N + BT - 1) / BT, BT>>>(
            zin, agg, b1[l], W2[l], b2[l], lv[l],
            (l < 4) ? W1[l + 1] : nullptr, zout, ng, sAcc, N);
        float* t = zin; zin = zout; zout = t;
    }

    final_kernel<<<(G + BT - 1) / BT, BT>>>(sAcc, cnt, out, G);
}

// round 2
// speedup vs baseline: 1.4463x; 1.4463x over previous
#include <cuda_runtime.h>
#include <math.h>
#include <stdint.h>

// ---------------------------------------------------------------------------
// NetGIN round 2: CSR-by-dst gather (no scatter atomics on the hot path).
//
// Per launch: build CSR (hist -> scan -> fill) once, then 5 fused layer
// kernels. Each layer kernel, one thread per node:
//   acc = sum_{e in CSR row} z[srcSorted[e]]          (register accum)
//   u = relu(z_i + acc + b1); o = relu(u@W2 + b2)
//   sAcc[graph(i)] += o . l        (warp-aggregated atomic; ng is sorted)
//   z_next = o @ W1_next
// Algebra as before: all edge traffic in dim-10 projected space.
// ---------------------------------------------------------------------------

#define NMAX   500000
#define EMAX   16000000
#define STRIDE 12
#define DIM    10
#define GMAX   8192
#define SCAN_B 1024

__device__ __align__(16) float g_zA[NMAX * STRIDE];
__device__ __align__(16) float g_zB[NMAX * STRIDE];
__device__ int   g_srcSorted[EMAX];
__device__ int   g_rowptr[NMAX + 1];
__device__ int   g_cursor[NMAX];
__device__ int   g_bsums[1024];
__device__ float g_s[GMAX];
__device__ float g_cnt[GMAX];

// ---------------- CSR build ----------------

__global__ void hist_kernel(const int* __restrict__ dst, int* __restrict__ rowptr, int E) {
    int e = blockIdx.x * blockDim.x + threadIdx.x;
    if (e < E) atomicAdd(&rowptr[dst[e] + 1], 1);
}

__global__ void scan_block_kernel(int* __restrict__ data, int n, int* __restrict__ bsums) {
    __shared__ int sh[SCAN_B];
    int gid = blockIdx.x * SCAN_B + threadIdx.x;
    int v = (gid < n) ? data[gid] : 0;
    sh[threadIdx.x] = v;
    __syncthreads();
    for (int off = 1; off < SCAN_B; off <<= 1) {
        int t = (threadIdx.x >= off) ? sh[threadIdx.x - off] : 0;
        __syncthreads();
        sh[threadIdx.x] += t;
        __syncthreads();
    }
    if (gid < n) data[gid] = sh[threadIdx.x];
    if (threadIdx.x == SCAN_B - 1) bsums[blockIdx.x] = sh[SCAN_B - 1];
}

__global__ void scan_sums_kernel(int* __restrict__ bsums, int nb) {
    __shared__ int sh[SCAN_B];
    int v = (threadIdx.x < nb) ? bsums[threadIdx.x] : 0;
    sh[threadIdx.x] = v;
    __syncthreads();
    for (int off = 1; off < SCAN_B; off <<= 1) {
        int t = (threadIdx.x >= off) ? sh[threadIdx.x - off] : 0;
        __syncthreads();
        sh[threadIdx.x] += t;
        __syncthreads();
    }
    if (threadIdx.x < nb) bsums[threadIdx.x] = sh[threadIdx.x] - v;  // exclusive
}

__global__ void scan_add_kernel(int* __restrict__ data, int n, const int* __restrict__ bsums) {
    int gid = blockIdx.x * SCAN_B + threadIdx.x;
    if (gid < n) data[gid] += bsums[blockIdx.x];
}

__global__ void fill_kernel(const int* __restrict__ src, const int* __restrict__ dst,
                            int* __restrict__ cursor, int* __restrict__ srcSorted, int E) {
    int e = blockIdx.x * blockDim.x + threadIdx.x;
    if (e < E) {
        int d = dst[e];
        int p = atomicAdd(&cursor[d], 1);
        srcSorted[p] = src[e];
    }
}

// ---------------- graph counts via binary search (ng is sorted) ------------

__global__ void count_bs_kernel(const int* __restrict__ ng, float* __restrict__ cnt,
                                float* __restrict__ sAcc, int N, int G) {
    int g = blockIdx.x * blockDim.x + threadIdx.x;
    if (g >= G) return;
    int lo = 0, hi = N;
    while (lo < hi) { int m = (lo + hi) >> 1; if (ng[m] < g) lo = m + 1; else hi = m; }
    int a = lo;
    lo = 0; hi = N;
    while (lo < hi) { int m = (lo + hi) >> 1; if (ng[m] < g + 1) lo = m + 1; else hi = m; }
    cnt[g] = (float)(lo - a);
    sAcc[g] = 0.0f;
}

__global__ void final_kernel(const float* __restrict__ s, const float* __restrict__ cnt,
                             float* __restrict__ out, int G) {
    int i = blockIdx.x * blockDim.x + threadIdx.x;
    if (i < G) {
        float v = s[i] / fmaxf(cnt[i], 1.0f);
        out[i] = 1.0f / (1.0f + expf(-v));
    }
}

// ---------------- layer-1 projection: z = h @ W1 (64 -> 10) ----------------

__global__ void proj1_kernel(const float* __restrict__ h, const float* __restrict__ W1,
                             float* __restrict__ z, int n) {
    int i = blockIdx.x * blockDim.x + threadIdx.x;
    if (i >= n) return;
    float acc[DIM];
#pragma unroll
    for (int d = 0; d < DIM; d++) acc[d] = 0.0f;
    const float4* hp = reinterpret_cast<const float4*>(h + (size_t)i * 64);
#pragma unroll
    for (int k4 = 0; k4 < 16; k4++) {
        float4 hv = __ldg(&hp[k4]);
        int k = k4 * 4;
#pragma unroll
        for (int d = 0; d < DIM; d++) {
            acc[d] += hv.x * W1[(k + 0) * DIM + d];
            acc[d] += hv.y * W1[(k + 1) * DIM + d];
            acc[d] += hv.z * W1[(k + 2) * DIM + d];
            acc[d] += hv.w * W1[(k + 3) * DIM + d];
        }
    }
    float* zp = z + (size_t)i * STRIDE;
#pragma unroll
    for (int d = 0; d < DIM; d++) zp[d] = acc[d];
}

// ---------------- fused layer: gather + MLP + readout + next projection ----

__device__ __forceinline__ void add_row(const float* __restrict__ z, int s, float acc[DIM]) {
    const float* zs = z + (size_t)s * STRIDE;
    float4 a = *reinterpret_cast<const float4*>(zs);
    float4 b = *reinterpret_cast<const float4*>(zs + 4);
    float2 c = *reinterpret_cast<const float2*>(zs + 8);
    acc[0] += a.x; acc[1] += a.y; acc[2] += a.z; acc[3] += a.w;
    acc[4] += b.x; acc[5] += b.y; acc[6] += b.z; acc[7] += b.w;
    acc[8] += c.x; acc[9] += c.y;
}

__global__ void layer_kernel(const float* __restrict__ z,
                             const int* __restrict__ rowptr,
                             const int* __restrict__ srcSorted,
                             const float* __restrict__ b1,
                             const float* __restrict__ W2,
                             const float* __restrict__ b2,
                             const float* __restrict__ lvec,
                             const float* __restrict__ W1n,   // null on last layer
                             float* __restrict__ znext,
                             const int* __restrict__ ng,
                             float* __restrict__ sAcc, int n) {
    int i = blockIdx.x * blockDim.x + threadIdx.x;
    bool valid = (i < n);

    float r = 0.0f;
    int g = -1;

    if (valid) {
        int beg = rowptr[i];
        int end = rowptr[i + 1];

        float acc[DIM];
#pragma unroll
        for (int d = 0; d < DIM; d++) acc[d] = 0.0f;

        int e = beg;
        // unroll by 4 for memory-level parallelism on the gathers
        for (; e + 4 <= end; e += 4) {
            int s0 = __ldg(&srcSorted[e + 0]);
            int s1 = __ldg(&srcSorted[e + 1]);
            int s2 = __ldg(&srcSorted[e + 2]);
            int s3 = __ldg(&srcSorted[e + 3]);
            add_row(z, s0, acc);
            add_row(z, s1, acc);
            add_row(z, s2, acc);
            add_row(z, s3, acc);
        }
        for (; e < end; e++) add_row(z, __ldg(&srcSorted[e]), acc);

        // self term + bias + relu
        const float* zp = z + (size_t)i * STRIDE;
        float u[DIM];
        {
            float4 z0 = *reinterpret_cast<const float4*>(zp);
            float4 z1 = *reinterpret_cast<const float4*>(zp + 4);
            float2 z2 = *reinterpret_cast<const float2*>(zp + 8);
            u[0] = fmaxf(z0.x + acc[0] + b1[0], 0.0f);
            u[1] = fmaxf(z0.y + acc[1] + b1[1], 0.0f);
            u[2] = fmaxf(z0.z + acc[2] + b1[2], 0.0f);
            u[3] = fmaxf(z0.w + acc[3] + b1[3], 0.0f);
            u[4] = fmaxf(z1.x + acc[4] + b1[4], 0.0f);
            u[5] = fmaxf(z1.y + acc[5] + b1[5], 0.0f);
            u[6] = fmaxf(z1.z + acc[6] + b1[6], 0.0f);
            u[7] = fmaxf(z1.w + acc[7] + b1[7], 0.0f);
            u[8] = fmaxf(z2.x + acc[8] + b1[8], 0.0f);
            u[9] = fmaxf(z2.y + acc[9] + b1[9], 0.0f);
        }

        float o[DIM];
#pragma unroll
        for (int d = 0; d < DIM; d++) {
            float a2 = b2[d];
#pragma unroll
            for (int k = 0; k < DIM; k++) a2 += u[k] * W2[k * DIM + d];
            o[d] = fmaxf(a2, 0.0f);
        }

#pragma unroll
        for (int d = 0; d < DIM; d++) r += o[d] * lvec[d];
        g = ng[i];

        if (W1n != nullptr) {
            float* zn = znext + (size_t)i * STRIDE;
#pragma unroll
            for (int d = 0; d < DIM; d++) {
                float a2 = 0.0f;
#pragma unroll
                for (int k = 0; k < DIM; k++) a2 += o[k] * W1n[k * DIM + d];
                zn[d] = a2;
            }
        }
    }

    // warp-aggregated readout atomic (ng is sorted -> usually uniform in warp)
    unsigned full = 0xffffffffu;
    int g0 = __shfl_sync(full, g, 0);
    bool allsame = __all_sync(full, (g == g0) || !valid);
    if (allsame) {
#pragma unroll
        for (int off = 16; off >= 1; off >>= 1) r += __shfl_xor_sync(full, r, off);
        if ((threadIdx.x & 31) == 0 && g0 >= 0) atomicAdd(&sAcc[g0], r);
    } else {
        if (valid) atomicAdd(&sAcc[g], r);
    }
}

// ---------------------------------------------------------------------------

extern "C" void kernel_launch(void* const* d_in, const int* in_sizes, int n_in,
                              void* d_out, int out_size) {
    const float* h   = (const float*)d_in[0];
    const int*   src = (const int*)d_in[1];
    const int*   dst = (const int*)d_in[2];
    const int*   ng  = (const int*)d_in[3];

    const float *W1[5], *b1[5], *W2[5], *b2[5], *lv[5];
    for (int i = 0; i < 5; i++) {
        W1[i] = (const float*)d_in[4 + 5 * i + 0];
        b1[i] = (const float*)d_in[4 + 5 * i + 1];
        W2[i] = (const float*)d_in[4 + 5 * i + 2];
        b2[i] = (const float*)d_in[4 + 5 * i + 3];
        lv[i] = (const float*)d_in[4 + 5 * i + 4];
    }

    int N = in_sizes[3];
    int E = in_sizes[1];
    int G = out_size;
    float* out = (float*)d_out;

    float *zA, *zB, *sAcc, *cnt;
    int *srcSorted, *rowptr, *cursor, *bsums;
    cudaGetSymbolAddress((void**)&zA,        g_zA);
    cudaGetSymbolAddress((void**)&zB,        g_zB);
    cudaGetSymbolAddress((void**)&srcSorted, g_srcSorted);
    cudaGetSymbolAddress((void**)&rowptr,    g_rowptr);
    cudaGetSymbolAddress((void**)&cursor,    g_cursor);
    cudaGetSymbolAddress((void**)&bsums,     g_bsums);
    cudaGetSymbolAddress((void**)&sAcc,      g_s);
    cudaGetSymbolAddress((void**)&cnt,       g_cnt);

    const int BT = 256;
    int nb = (N + 1 + SCAN_B - 1) / SCAN_B;

    // ---- build CSR by dst ----
    cudaMemsetAsync(rowptr, 0, (size_t)(N + 1) * sizeof(int), 0);
    hist_kernel<<<(E + BT - 1) / BT, BT>>>(dst, rowptr, E);
    scan_block_kernel<<<nb, SCAN_B>>>(rowptr, N + 1, bsums);
    scan_sums_kernel<<<1, SCAN_B>>>(bsums, nb);
    scan_add_kernel<<<nb, SCAN_B>>>(rowptr, N + 1, bsums);
    cudaMemcpyAsync(cursor, rowptr, (size_t)N * sizeof(int), cudaMemcpyDeviceToDevice, 0);
    fill_kernel<<<(E + BT - 1) / BT, BT>>>(src, dst, cursor, srcSorted, E);

    // ---- graph counts + zero accumulators ----
    count_bs_kernel<<<(G + BT - 1) / BT, BT>>>(ng, cnt, sAcc, N, G);

    // ---- layer-1 projection ----
    proj1_kernel<<<(N + 127) / 128, 128>>>(h, W1[0], zA, N);

    // ---- 5 fused layers ----
    float* zin = zA;
    float* zout = zB;
    for (int l = 0; l < 5; l++) {
        layer_kernel<<<(N + BT - 1) / BT, BT>>>(
            zin, rowptr, srcSorted, b1[l], W2[l], b2[l], lv[l],
            (l < 4) ? W1[l + 1] : nullptr, zout, ng, sAcc, N);
        float* t = zin; zin = zout; zout = t;
    }

    final_kernel<<<(G + BT - 1) / BT, BT>>>(sAcc, cnt, out, G);
}

// round 3
// speedup vs baseline: 1.8089x; 1.2507x over previous
#include <cuda_runtime.h>
#include <cuda_fp16.h>
#include <math.h>
#include <stdint.h>

// ---------------------------------------------------------------------------
// NetGIN round 3: CSR-by-dst gather with fp16 z-storage.
// z rows: 10 halves padded to 16 (32 B = exactly one L2 sector, 32B-aligned)
// -> each neighbor gather touches ONE sector instead of two.
// Accumulation and all MLP math stay fp32.
// ---------------------------------------------------------------------------

#define NMAX     500000
#define EMAX     16000000
#define STRIDE_H 16          // halves per row (32 bytes)
#define DIM      10
#define GMAX     8192
#define SCAN_B   1024

__device__ __align__(32) __half g_zA[NMAX * STRIDE_H];
__device__ __align__(32) __half g_zB[NMAX * STRIDE_H];
__device__ int   g_srcSorted[EMAX];
__device__ int   g_rowptr[NMAX + 1];
__device__ int   g_cursor[NMAX];
__device__ int   g_bsums[1024];
__device__ float g_s[GMAX];
__device__ float g_cnt[GMAX];

// ---------------- CSR build ----------------

__global__ void hist_kernel(const int* __restrict__ dst, int* __restrict__ rowptr, int E) {
    int e = blockIdx.x * blockDim.x + threadIdx.x;
    if (e < E) atomicAdd(&rowptr[dst[e] + 1], 1);
}

__global__ void scan_block_kernel(int* __restrict__ data, int n, int* __restrict__ bsums) {
    __shared__ int sh[SCAN_B];
    int gid = blockIdx.x * SCAN_B + threadIdx.x;
    int v = (gid < n) ? data[gid] : 0;
    sh[threadIdx.x] = v;
    __syncthreads();
    for (int off = 1; off < SCAN_B; off <<= 1) {
        int t = (threadIdx.x >= off) ? sh[threadIdx.x - off] : 0;
        __syncthreads();
        sh[threadIdx.x] += t;
        __syncthreads();
    }
    if (gid < n) data[gid] = sh[threadIdx.x];
    if (threadIdx.x == SCAN_B - 1) bsums[blockIdx.x] = sh[SCAN_B - 1];
}

__global__ void scan_sums_kernel(int* __restrict__ bsums, int nb) {
    __shared__ int sh[SCAN_B];
    int v = (threadIdx.x < nb) ? bsums[threadIdx.x] : 0;
    sh[threadIdx.x] = v;
    __syncthreads();
    for (int off = 1; off < SCAN_B; off <<= 1) {
        int t = (threadIdx.x >= off) ? sh[threadIdx.x - off] : 0;
        __syncthreads();
        sh[threadIdx.x] += t;
        __syncthreads();
    }
    if (threadIdx.x < nb) bsums[threadIdx.x] = sh[threadIdx.x] - v;  // exclusive
}

__global__ void scan_add_kernel(int* __restrict__ data, int n, const int* __restrict__ bsums) {
    int gid = blockIdx.x * SCAN_B + threadIdx.x;
    if (gid < n) data[gid] += bsums[blockIdx.x];
}

__global__ void fill_kernel(const int* __restrict__ src, const int* __restrict__ dst,
                            int* __restrict__ cursor, int* __restrict__ srcSorted, int E) {
    int e = blockIdx.x * blockDim.x + threadIdx.x;
    if (e < E) {
        int d = dst[e];
        int p = atomicAdd(&cursor[d], 1);
        srcSorted[p] = src[e];
    }
}

// ---------------- graph counts via binary search (ng is sorted) ------------

__global__ void count_bs_kernel(const int* __restrict__ ng, float* __restrict__ cnt,
                                float* __restrict__ sAcc, int N, int G) {
    int g = blockIdx.x * blockDim.x + threadIdx.x;
    if (g >= G) return;
    int lo = 0, hi = N;
    while (lo < hi) { int m = (lo + hi) >> 1; if (ng[m] < g) lo = m + 1; else hi = m; }
    int a = lo;
    lo = 0; hi = N;
    while (lo < hi) { int m = (lo + hi) >> 1; if (ng[m] < g + 1) lo = m + 1; else hi = m; }
    cnt[g] = (float)(lo - a);
    sAcc[g] = 0.0f;
}

__global__ void final_kernel(const float* __restrict__ s, const float* __restrict__ cnt,
                             float* __restrict__ out, int G) {
    int i = blockIdx.x * blockDim.x + threadIdx.x;
    if (i < G) {
        float v = s[i] / fmaxf(cnt[i], 1.0f);
        out[i] = 1.0f / (1.0f + expf(-v));
    }
}

// ---------------- fp16 row pack/unpack helpers ----------------

__device__ __forceinline__ void store_row_h(__half* __restrict__ z, int i, const float v[DIM]) {
    __half2* zp = reinterpret_cast<__half2*>(z + (size_t)i * STRIDE_H);
    zp[0] = __floats2half2_rn(v[0], v[1]);
    zp[1] = __floats2half2_rn(v[2], v[3]);
    zp[2] = __floats2half2_rn(v[4], v[5]);
    zp[3] = __floats2half2_rn(v[6], v[7]);
    zp[4] = __floats2half2_rn(v[8], v[9]);
}

__device__ __forceinline__ void add_row_h(const __half* __restrict__ z, int s, float acc[DIM]) {
    const __half* zs = z + (size_t)s * STRIDE_H;
    uint4 a = __ldg(reinterpret_cast<const uint4*>(zs));       // halves 0..7
    uint32_t b = __ldg(reinterpret_cast<const uint32_t*>(zs + 8)); // halves 8..9
    float2 f;
    f = __half22float2(*reinterpret_cast<__half2*>(&a.x)); acc[0] += f.x; acc[1] += f.y;
    f = __half22float2(*reinterpret_cast<__half2*>(&a.y)); acc[2] += f.x; acc[3] += f.y;
    f = __half22float2(*reinterpret_cast<__half2*>(&a.z)); acc[4] += f.x; acc[5] += f.y;
    f = __half22float2(*reinterpret_cast<__half2*>(&a.w)); acc[6] += f.x; acc[7] += f.y;
    f = __half22float2(*reinterpret_cast<__half2*>(&b));   acc[8] += f.x; acc[9] += f.y;
}

// ---------------- layer-1 projection: z = h @ W1 (64 -> 10) ----------------

__global__ void proj1_kernel(const float* __restrict__ h, const float* __restrict__ W1,
                             __half* __restrict__ z, int n) {
    int i = blockIdx.x * blockDim.x + threadIdx.x;
    if (i >= n) return;
    float acc[DIM];
#pragma unroll
    for (int d = 0; d < DIM; d++) acc[d] = 0.0f;
    const float4* hp = reinterpret_cast<const float4*>(h + (size_t)i * 64);
#pragma unroll
    for (int k4 = 0; k4 < 16; k4++) {
        float4 hv = __ldg(&hp[k4]);
        int k = k4 * 4;
#pragma unroll
        for (int d = 0; d < DIM; d++) {
            acc[d] += hv.x * W1[(k + 0) * DIM + d];
            acc[d] += hv.y * W1[(k + 1) * DIM + d];
            acc[d] += hv.z * W1[(k + 2) * DIM + d];
            acc[d] += hv.w * W1[(k + 3) * DIM + d];
        }
    }
    store_row_h(z, i, acc);
}

// ---------------- fused layer: gather + MLP + readout + next projection ----

__global__ void __launch_bounds__(256)
layer_kernel(const __half* __restrict__ z,
             const int* __restrict__ rowptr,
             const int* __restrict__ srcSorted,
             const float* __restrict__ b1,
             const float* __restrict__ W2,
             const float* __restrict__ b2,
             const float* __restrict__ lvec,
             const float* __restrict__ W1n,   // null on last layer
             __half* __restrict__ znext,
             const int* __restrict__ ng,
             float* __restrict__ sAcc, int n) {
    int i = blockIdx.x * blockDim.x + threadIdx.x;
    bool valid = (i < n);

    float r = 0.0f;
    int g = -1;

    if (valid) {
        int beg = rowptr[i];
        int end = rowptr[i + 1];

        float acc[DIM];
#pragma unroll
        for (int d = 0; d < DIM; d++) acc[d] = 0.0f;

        int e = beg;
        for (; e + 4 <= end; e += 4) {
            int s0 = __ldg(&srcSorted[e + 0]);
            int s1 = __ldg(&srcSorted[e + 1]);
            int s2 = __ldg(&srcSorted[e + 2]);
            int s3 = __ldg(&srcSorted[e + 3]);
            add_row_h(z, s0, acc);
            add_row_h(z, s1, acc);
            add_row_h(z, s2, acc);
            add_row_h(z, s3, acc);
        }
        for (; e < end; e++) add_row_h(z, __ldg(&srcSorted[e]), acc);

        // self term + bias + relu
        float u[DIM];
        {
            float self[DIM];
#pragma unroll
            for (int d = 0; d < DIM; d++) self[d] = 0.0f;
            add_row_h(z, i, self);
#pragma unroll
            for (int d = 0; d < DIM; d++)
                u[d] = fmaxf(self[d] + acc[d] + b1[d], 0.0f);
        }

        float o[DIM];
#pragma unroll
        for (int d = 0; d < DIM; d++) {
            float a2 = b2[d];
#pragma unroll
            for (int k = 0; k < DIM; k++) a2 += u[k] * W2[k * DIM + d];
            o[d] = fmaxf(a2, 0.0f);
        }

#pragma unroll
        for (int d = 0; d < DIM; d++) r += o[d] * lvec[d];
        g = ng[i];

        if (W1n != nullptr) {
            float zn[DIM];
#pragma unroll
            for (int d = 0; d < DIM; d++) {
                float a2 = 0.0f;
#pragma unroll
                for (int k = 0; k < DIM; k++) a2 += o[k] * W1n[k * DIM + d];
                zn[d] = a2;
            }
            store_row_h(znext, i, zn);
        }
    }

    // warp-aggregated readout atomic (ng is sorted -> usually uniform in warp)
    unsigned full = 0xffffffffu;
    int g0 = __shfl_sync(full, g, 0);
    bool allsame = __all_sync(full, (g == g0) || !valid);
    if (allsame) {
#pragma unroll
        for (int off = 16; off >= 1; off >>= 1) r += __shfl_xor_sync(full, r, off);
        if ((threadIdx.x & 31) == 0 && g0 >= 0) atomicAdd(&sAcc[g0], r);
    } else {
        if (valid) atomicAdd(&sAcc[g], r);
    }
}

// ---------------------------------------------------------------------------

extern "C" void kernel_launch(void* const* d_in, const int* in_sizes, int n_in,
                              void* d_out, int out_size) {
    const float* h   = (const float*)d_in[0];
    const int*   src = (const int*)d_in[1];
    const int*   dst = (const int*)d_in[2];
    const int*   ng  = (const int*)d_in[3];

    const float *W1[5], *b1[5], *W2[5], *b2[5], *lv[5];
    for (int i = 0; i < 5; i++) {
        W1[i] = (const float*)d_in[4 + 5 * i + 0];
        b1[i] = (const float*)d_in[4 + 5 * i + 1];
        W2[i] = (const float*)d_in[4 + 5 * i + 2];
        b2[i] = (const float*)d_in[4 + 5 * i + 3];
        lv[i] = (const float*)d_in[4 + 5 * i + 4];
    }

    int N = in_sizes[3];
    int E = in_sizes[1];
    int G = out_size;
    float* out = (float*)d_out;

    __half *zA, *zB;
    float *sAcc, *cnt;
    int *srcSorted, *rowptr, *cursor, *bsums;
    cudaGetSymbolAddress((void**)&zA,        g_zA);
    cudaGetSymbolAddress((void**)&zB,        g_zB);
    cudaGetSymbolAddress((void**)&srcSorted, g_srcSorted);
    cudaGetSymbolAddress((void**)&rowptr,    g_rowptr);
    cudaGetSymbolAddress((void**)&cursor,    g_cursor);
    cudaGetSymbolAddress((void**)&bsums,     g_bsums);
    cudaGetSymbolAddress((void**)&sAcc,      g_s);
    cudaGetSymbolAddress((void**)&cnt,       g_cnt);

    const int BT = 256;
    int nb = (N + 1 + SCAN_B - 1) / SCAN_B;

    // ---- build CSR by dst ----
    cudaMemsetAsync(rowptr, 0, (size_t)(N + 1) * sizeof(int), 0);
    hist_kernel<<<(E + BT - 1) / BT, BT>>>(dst, rowptr, E);
    scan_block_kernel<<<nb, SCAN_B>>>(rowptr, N + 1, bsums);
    scan_sums_kernel<<<1, SCAN_B>>>(bsums, nb);
    scan_add_kernel<<<nb, SCAN_B>>>(rowptr, N + 1, bsums);
    cudaMemcpyAsync(cursor, rowptr, (size_t)N * sizeof(int), cudaMemcpyDeviceToDevice, 0);
    fill_kernel<<<(E + BT - 1) / BT, BT>>>(src, dst, cursor, srcSorted, E);

    // ---- graph counts + zero accumulators ----
    count_bs_kernel<<<(G + BT - 1) / BT, BT>>>(ng, cnt, sAcc, N, G);

    // ---- layer-1 projection ----
    proj1_kernel<<<(N + 127) / 128, 128>>>(h, W1[0], zA, N);

    // ---- 5 fused layers ----
    __half* zin = zA;
    __half* zout = zB;
    for (int l = 0; l < 5; l++) {
        layer_kernel<<<(N + BT - 1) / BT, BT>>>(
            zin, rowptr, srcSorted, b1[l], W2[l], b2[l], lv[l],
            (l < 4) ? W1[l + 1] : nullptr, zout, ng, sAcc, N);
        __half* t = zin; zin = zout; zout = t;
    }

    final_kernel<<<(G + BT - 1) / BT, BT>>>(sAcc, cnt, out, G);
}

// round 4
// speedup vs baseline: 1.9762x; 1.0925x over previous
#include <cuda_runtime.h>
#include <cuda_fp16.h>
#include <math.h>
#include <stdint.h>

// ---------------------------------------------------------------------------
// NetGIN round 4: fp16 CSR gather + single-pass lookback scan + fused init.
// Launch order: proj_init, hist, scan(lookback), fill, 5x layer, final.
// (5th launch = layer1, so ncu's skip-5 capture lands on the hot kernel.)
// ---------------------------------------------------------------------------

#define NMAX     500000
#define EMAX     16000000
#define STRIDE_H 16          // halves per row (32 B = 1 sector)
#define DIM      10
#define GMAX     8192
#define TILE     1024
#define NDESC    1024

__device__ __align__(32) __half g_zA[NMAX * STRIDE_H];
__device__ __align__(32) __half g_zB[NMAX * STRIDE_H];
__device__ __align__(16) int g_srcSorted[EMAX];
__device__ int   g_rowptr[NMAX + 1];
__device__ int   g_cursor[NMAX];
__device__ unsigned long long g_desc[NDESC];
__device__ float g_s[GMAX];
__device__ float g_cnt[GMAX];

// ---------------- fp16 row helpers ----------------

__device__ __forceinline__ void store_row_h(__half* __restrict__ z, int i, const float v[DIM]) {
    __half2* zp = reinterpret_cast<__half2*>(z + (size_t)i * STRIDE_H);
    zp[0] = __floats2half2_rn(v[0], v[1]);
    zp[1] = __floats2half2_rn(v[2], v[3]);
    zp[2] = __floats2half2_rn(v[4], v[5]);
    zp[3] = __floats2half2_rn(v[6], v[7]);
    zp[4] = __floats2half2_rn(v[8], v[9]);
}

__device__ __forceinline__ void add_row_h(const __half* __restrict__ z, int s, float acc[DIM]) {
    const __half* zs = z + (size_t)s * STRIDE_H;
    uint4 a = __ldg(reinterpret_cast<const uint4*>(zs));
    uint32_t b = __ldg(reinterpret_cast<const uint32_t*>(zs + 8));
    float2 f;
    f = __half22float2(*reinterpret_cast<__half2*>(&a.x)); acc[0] += f.x; acc[1] += f.y;
    f = __half22float2(*reinterpret_cast<__half2*>(&a.y)); acc[2] += f.x; acc[3] += f.y;
    f = __half22float2(*reinterpret_cast<__half2*>(&a.z)); acc[4] += f.x; acc[5] += f.y;
    f = __half22float2(*reinterpret_cast<__half2*>(&a.w)); acc[6] += f.x; acc[7] += f.y;
    f = __half22float2(*reinterpret_cast<__half2*>(&b));   acc[8] += f.x; acc[9] += f.y;
}

// ---------------- K1: proj1 + all per-launch init (fused) ----------------
// - z = h @ W1 (64 -> 10), fp16 store
// - zero rowptr[0..N], zero lookback descriptors
// - per-graph counts via binary search over sorted node_graph; zero sAcc

__global__ void proj_init_kernel(const float* __restrict__ h,
                                 const float* __restrict__ W1,
                                 __half* __restrict__ z,
                                 int* __restrict__ rowptr,
                                 unsigned long long* __restrict__ desc,
                                 const int* __restrict__ ng,
                                 float* __restrict__ cnt,
                                 float* __restrict__ sAcc,
                                 int N, int G) {
    int i = blockIdx.x * blockDim.x + threadIdx.x;

    if (i < NDESC) desc[i] = 0ULL;
    if (i < N) rowptr[i] = 0;
    if (i == 0) rowptr[N] = 0;

    if (i < G) {
        int lo = 0, hi = N;
        while (lo < hi) { int m = (lo + hi) >> 1; if (ng[m] < i) lo = m + 1; else hi = m; }
        int a = lo;
        lo = 0; hi = N;
        while (lo < hi) { int m = (lo + hi) >> 1; if (ng[m] < i + 1) lo = m + 1; else hi = m; }
        cnt[i] = (float)(lo - a);
        sAcc[i] = 0.0f;
    }

    if (i >= N) return;

    float acc[DIM];
#pragma unroll
    for (int d = 0; d < DIM; d++) acc[d] = 0.0f;
    const float4* hp = reinterpret_cast<const float4*>(h + (size_t)i * 64);
#pragma unroll
    for (int k4 = 0; k4 < 16; k4++) {
        float4 hv = __ldg(&hp[k4]);
        int k = k4 * 4;
#pragma unroll
        for (int d = 0; d < DIM; d++) {
            acc[d] += hv.x * W1[(k + 0) * DIM + d];
            acc[d] += hv.y * W1[(k + 1) * DIM + d];
            acc[d] += hv.z * W1[(k + 2) * DIM + d];
            acc[d] += hv.w * W1[(k + 3) * DIM + d];
        }
    }
    store_row_h(z, i, acc);
}

// ---------------- K2: histogram of dst ----------------

__global__ void hist_kernel(const int* __restrict__ dst, int* __restrict__ rowptr, int E) {
    int e = blockIdx.x * blockDim.x + threadIdx.x;
    if (e < E) atomicAdd(&rowptr[dst[e] + 1], 1);
}

// ---------------- K3: single-pass inclusive scan (decoupled lookback) ------
// desc[p] = (flag << 32) | value;  flag: 0=invalid, 1=aggregate, 2=prefix.
// Also writes cursor[i] = rowptr[i] for i < N (fill's write cursors).

__global__ void __launch_bounds__(TILE)
scan_kernel(int* __restrict__ rowptr, int n,
            unsigned long long* __restrict__ desc,
            int* __restrict__ cursor) {
    __shared__ int sh[TILE];
    __shared__ int s_excl;
    int part = blockIdx.x;
    int gid = part * TILE + threadIdx.x;

    int v = (gid < n) ? rowptr[gid] : 0;
    sh[threadIdx.x] = v;
    __syncthreads();
    for (int off = 1; off < TILE; off <<= 1) {
        int t = (threadIdx.x >= off) ? sh[threadIdx.x - off] : 0;
        __syncthreads();
        sh[threadIdx.x] += t;
        __syncthreads();
    }
    int total = sh[TILE - 1];

    if (threadIdx.x == 0) {
        if (part == 0) {
            s_excl = 0;
            atomicExch(&desc[0], (2ULL << 32) | (unsigned int)total);
        } else {
            atomicExch(&desc[part], (1ULL << 32) | (unsigned int)total);
        }
    }

    if (part > 0 && threadIdx.x < 32) {
        int lane = threadIdx.x;
        int sum = 0;
        int base = part;
        bool done = false;
        while (!done) {
            int idx = base - 32 + lane;
            int flag, val;
            if (idx < 0) { flag = 2; val = 0; }
            else {
                unsigned long long d;
                do {
                    d = *((volatile unsigned long long*)&desc[idx]);
                    flag = (int)(d >> 32);
                } while (flag == 0);
                val = (int)(d & 0xffffffffULL);
            }
            unsigned pmask = __ballot_sync(0xffffffffu, flag == 2);
            int contrib;
            if (pmask) {
                int hi = 31 - __clz(pmask);           // prefix closest to part
                contrib = (lane >= hi) ? val : 0;
                done = true;
            } else {
                contrib = val;
                base -= 32;
            }
#pragma unroll
            for (int off = 16; off >= 1; off >>= 1)
                contrib += __shfl_xor_sync(0xffffffffu, contrib, off);
            sum += contrib;
        }
        if (lane == 0) {
            s_excl = sum;
            atomicExch(&desc[part], (2ULL << 32) | (unsigned int)(sum + total));
        }
    }
    __syncthreads();

    int out = sh[threadIdx.x] + s_excl;
    if (gid < n) rowptr[gid] = out;
    if (gid < n - 1) cursor[gid] = out;   // n = N+1
}

// ---------------- K4: CSR fill ----------------

__global__ void fill_kernel(const int* __restrict__ src, const int* __restrict__ dst,
                            int* __restrict__ cursor, int* __restrict__ srcSorted, int E) {
    int e = blockIdx.x * blockDim.x + threadIdx.x;
    if (e < E) {
        int d = dst[e];
        int p = atomicAdd(&cursor[d], 1);
        srcSorted[p] = src[e];
    }
}

// ---------------- K5..K9: fused layer ----------------

__global__ void __launch_bounds__(256)
layer_kernel(const __half* __restrict__ z,
             const int* __restrict__ rowptr,
             const int* __restrict__ srcSorted,
             const float* __restrict__ b1,
             const float* __restrict__ W2,
             const float* __restrict__ b2,
             const float* __restrict__ lvec,
             const float* __restrict__ W1n,   // null on last layer
             __half* __restrict__ znext,
             const int* __restrict__ ng,
             float* __restrict__ sAcc, int n) {
    int i = blockIdx.x * blockDim.x + threadIdx.x;
    bool valid = (i < n);

    float r = 0.0f;
    int g = -1;

    if (valid) {
        int beg = rowptr[i];
        int end = rowptr[i + 1];

        float acc[DIM];
#pragma unroll
        for (int d = 0; d < DIM; d++) acc[d] = 0.0f;

        // aligned int4 index loads with range predication
        int a = beg & ~3;
        for (; a < end; a += 4) {
            int4 v = __ldg(reinterpret_cast<const int4*>(srcSorted + a));
            if (a     >= beg && a     < end) add_row_h(z, v.x, acc);
            if (a + 1 >= beg && a + 1 < end) add_row_h(z, v.y, acc);
            if (a + 2 >= beg && a + 2 < end) add_row_h(z, v.z, acc);
            if (a + 3 >= beg && a + 3 < end) add_row_h(z, v.w, acc);
        }

        // self term + bias + relu
        float u[DIM];
        {
            float self[DIM];
#pragma unroll
            for (int d = 0; d < DIM; d++) self[d] = 0.0f;
            add_row_h(z, i, self);
#pragma unroll
            for (int d = 0; d < DIM; d++)
                u[d] = fmaxf(self[d] + acc[d] + b1[d], 0.0f);
        }

        float o[DIM];
#pragma unroll
        for (int d = 0; d < DIM; d++) {
            float a2 = b2[d];
#pragma unroll
            for (int k = 0; k < DIM; k++) a2 += u[k] * W2[k * DIM + d];
            o[d] = fmaxf(a2, 0.0f);
        }

#pragma unroll
        for (int d = 0; d < DIM; d++) r += o[d] * lvec[d];
        g = ng[i];

        if (W1n != nullptr) {
            float zn[DIM];
#pragma unroll
            for (int d = 0; d < DIM; d++) {
                float a2 = 0.0f;
#pragma unroll
                for (int k = 0; k < DIM; k++) a2 += o[k] * W1n[k * DIM + d];
                zn[d] = a2;
            }
            store_row_h(znext, i, zn);
        }
    }

    // warp-aggregated readout atomic (ng sorted -> usually uniform per warp)
    unsigned full = 0xffffffffu;
    int g0 = __shfl_sync(full, g, 0);
    bool allsame = __all_sync(full, (g == g0) || !valid);
    if (allsame) {
#pragma unroll
        for (int off = 16; off >= 1; off >>= 1) r += __shfl_xor_sync(full, r, off);
        if ((threadIdx.x & 31) == 0 && g0 >= 0) atomicAdd(&sAcc[g0], r);
    } else {
        if (valid) atomicAdd(&sAcc[g], r);
    }
}

// ---------------- K10: final ----------------

__global__ void final_kernel(const float* __restrict__ s, const float* __restrict__ cnt,
                             float* __restrict__ out, int G) {
    int i = blockIdx.x * blockDim.x + threadIdx.x;
    if (i < G) {
        float v = s[i] / fmaxf(cnt[i], 1.0f);
        out[i] = 1.0f / (1.0f + expf(-v));
    }
}

// ---------------------------------------------------------------------------

extern "C" void kernel_launch(void* const* d_in, const int* in_sizes, int n_in,
                              void* d_out, int out_size) {
    const float* h   = (const float*)d_in[0];
    const int*   src = (const int*)d_in[1];
    const int*   dst = (const int*)d_in[2];
    const int*   ng  = (const int*)d_in[3];

    const float *W1[5], *b1[5], *W2[5], *b2[5], *lv[5];
    for (int i = 0; i < 5; i++) {
        W1[i] = (const float*)d_in[4 + 5 * i + 0];
        b1[i] = (const float*)d_in[4 + 5 * i + 1];
        W2[i] = (const float*)d_in[4 + 5 * i + 2];
        b2[i] = (const float*)d_in[4 + 5 * i + 3];
        lv[i] = (const float*)d_in[4 + 5 * i + 4];
    }

    int N = in_sizes[3];
    int E = in_sizes[1];
    int G = out_size;
    float* out = (float*)d_out;

    __half *zA, *zB;
    float *sAcc, *cnt;
    int *srcSorted, *rowptr, *cursor;
    unsigned long long* desc;
    cudaGetSymbolAddress((void**)&zA,        g_zA);
    cudaGetSymbolAddress((void**)&zB,        g_zB);
    cudaGetSymbolAddress((void**)&srcSorted, g_srcSorted);
    cudaGetSymbolAddress((void**)&rowptr,    g_rowptr);
    cudaGetSymbolAddress((void**)&cursor,    g_cursor);
    cudaGetSymbolAddress((void**)&desc,      g_desc);
    cudaGetSymbolAddress((void**)&sAcc,      g_s);
    cudaGetSymbolAddress((void**)&cnt,       g_cnt);

    const int BT = 256;
    int nScan = N + 1;
    int nb = (nScan + TILE - 1) / TILE;

    // 1: proj1 + init (zero rowptr/desc, graph counts, zero sAcc)
    proj_init_kernel<<<(N + BT - 1) / BT, BT>>>(h, W1[0], zA, rowptr, desc, ng, cnt, sAcc, N, G);
    // 2: histogram
    hist_kernel<<<(E + BT - 1) / BT, BT>>>(dst, rowptr, E);
    // 3: single-pass scan (also writes cursor)
    scan_kernel<<<nb, TILE>>>(rowptr, nScan, desc, cursor);
    // 4: CSR fill
    fill_kernel<<<(E + BT - 1) / BT, BT>>>(src, dst, cursor, srcSorted, E);

    // 5..9: fused layers  (launch #5 = layer1 -> ncu capture target)
    __half* zin = zA;
    __half* zout = zB;
    for (int l = 0; l < 5; l++) {
        layer_kernel<<<(N + BT - 1) / BT, BT>>>(
            zin, rowptr, srcSorted, b1[l], W2[l], b2[l], lv[l],
            (l < 4) ? W1[l + 1] : nullptr, zout, ng, sAcc, N);
        __half* t = zin; zin = zout; zout = t;
    }

    // 10: final
    final_kernel<<<(G + BT - 1) / BT, BT>>>(sAcc, cnt, out, G);
}